// round 15
// baseline (speedup 1.0000x reference)
#include <cuda_runtime.h>
#include <cuda_fp16.h>
#include <cstdint>

#define B_    8
#define HW_   32
#define C_    32
#define F_    64
#define FQ_   16
#define HO_   30
#define WO_   30
#define K_    288
#define KPADH 296
#define SCALE 2048.0f
#define INVSC (1.0f / 2048.0f)

__device__ __forceinline__ unsigned h2u(__half2 h)
{
    unsigned u; memcpy(&u, &h, 4); return u;
}
__device__ __forceinline__ __half2 f_as_h2(float f)
{
    __half2 h; unsigned u = __float_as_uint(f); memcpy(&h, &u, 4); return h;
}
__device__ __forceinline__ unsigned packs16(float a, float b)
{
    int ia = __float2int_rn(a * SCALE);
    int ib = __float2int_rn(b * SCALE);
    return ((unsigned)ia & 0xffffu) | ((unsigned)ib << 16);
}

// one half2 step fp16 (fma-leaning) ; one s16x2 step DPX (alu-only)
#define AH(mx, mn, pc, wc)                                                   \
    do { __half2 s_ = __hadd2(f_as_h2(pc), f_as_h2(wc));                     \
         mx = __hmax2(mx, s_); mn = __hmin2(mn, s_); } while (0)
#define AI(mx, mn, pc, wc)                                                   \
    do { mx = __viaddmax_s16x2(pc, wc, mx);                                  \
         mn = __viaddmin_s16x2(pc, wc, mn); } while (0)

// interleaved 8-channel step: 4 fp16 half2 + 4 dpx s16x2, alternating
#define ACC_MIX(t, ph, pi)                                                   \
    do {                                                                     \
        AH(mx2[t], mn2[t], (ph).x, wvh.x);  AI(mxi[t], mni[t], (pi).x, wvi.x); \
        AH(mx2[t], mn2[t], (ph).y, wvh.y);  AI(mxi[t], mni[t], (pi).y, wvi.y); \
        AH(mx2[t], mn2[t], (ph).z, wvh.z);  AI(mxi[t], mni[t], (pi).z, wvi.z); \
        AH(mx2[t], mn2[t], (ph).w, wvh.w);  AI(mxi[t], mni[t], (pi).w, wvi.w); \
    } while (0)

__global__ __launch_bounds__(128, 6)
void tropconv_hyb(const float* __restrict__ x,
                  const float* __restrict__ w,
                  const float* __restrict__ bias,
                  float* __restrict__ out)
{
    // channels 0..15 stored as half; channels 16..31 as s16
    __shared__ __align__(16) unsigned short w_sm[FQ_ * KPADH];   // [16][296]
    __shared__ __align__(16) unsigned short x_sm[3 * HW_ * C_];  // [3][32][32]

    const int tid = threadIdx.x;
    const int fq  = blockIdx.x & 3;
    const int row = blockIdx.x >> 2;          // b*30 + ho
    const int ho  = row % HO_;
    const int b   = row / HO_;

    // ---- inline w transpose+convert, k-paired, format by (k&16) ----
    #pragma unroll
    for (int idx = tid; idx < 576; idx += 128) {
        int k  = (idx >> 2) * 2;
        int f4 = idx & 3;
        float4 v0 = *(const float4*)(w + (k    ) * F_ + fq * FQ_ + f4 * 4);
        float4 v1 = *(const float4*)(w + (k + 1) * F_ + fq * FQ_ + f4 * 4);
        bool fp16fmt = (k & 16) == 0;
        unsigned short* base = w_sm + (f4 * 4) * KPADH + k;
        if (fp16fmt) {
            *(unsigned*)(base + 0 * KPADH) = h2u(__floats2half2_rn(v0.x, v1.x));
            *(unsigned*)(base + 1 * KPADH) = h2u(__floats2half2_rn(v0.y, v1.y));
            *(unsigned*)(base + 2 * KPADH) = h2u(__floats2half2_rn(v0.z, v1.z));
            *(unsigned*)(base + 3 * KPADH) = h2u(__floats2half2_rn(v0.w, v1.w));
        } else {
            *(unsigned*)(base + 0 * KPADH) = packs16(v0.x, v1.x);
            *(unsigned*)(base + 1 * KPADH) = packs16(v0.y, v1.y);
            *(unsigned*)(base + 2 * KPADH) = packs16(v0.z, v1.z);
            *(unsigned*)(base + 3 * KPADH) = packs16(v0.w, v1.w);
        }
    }
    // ---- inline x convert: 768 float4; (idx&4)==0 -> fp16 half, else s16 ----
    {
        const float4* src = (const float4*)(x + (b * HW_ + ho) * (HW_ * C_));
        uint2* dst = (uint2*)x_sm;
        #pragma unroll
        for (int idx = tid; idx < 768; idx += 128) {
            float4 v = src[idx];
            if ((idx & 4) == 0)
                dst[idx] = make_uint2(h2u(__floats2half2_rn(v.x, v.y)),
                                      h2u(__floats2half2_rn(v.z, v.w)));
            else
                dst[idx] = make_uint2(packs16(v.x, v.y), packs16(v.z, v.w));
        }
    }
    __syncthreads();

    const int fl   = tid & 15;
    const int slot = tid >> 4;
    const int wo_base = slot * 4;

    const char* wrowb = (const char*)w_sm + fl * (KPADH * 2);
    const char* xb = (const char*)x_sm;

    int coff[6];
    #pragma unroll
    for (int u = 0; u < 6; ++u) {
        int col = wo_base + u;
        if (col > 31) col = 31;               // garbage only feeds masked stores
        coff[u] = col * 64;
    }

    const __half2 HNEG = __float2half2_rn(-65504.0f);
    const __half2 HPOS = __float2half2_rn(65504.0f);
    __half2 mx2[4], mn2[4];
    unsigned mxi[4], mni[4];
    #pragma unroll
    for (int t = 0; t < 4; ++t) {
        mx2[t] = HNEG; mn2[t] = HPOS;
        mxi[t] = 0x80008000u; mni[t] = 0x7fff7fffu;
    }

    #pragma unroll 1
    for (int cc = 0; cc < 2; ++cc) {
        const int ch = cc;        // fp16 chunk (channels 0..15)
        const int ci = cc + 2;    // dpx  chunk (channels 16..31)
        #pragma unroll
        for (int i = 0; i < 3; ++i) {
            const char* cbh = xb + i * 2048 + ch * 16;
            const char* cbi = xb + i * 2048 + ci * 16;
            // dual rolling windows (4+4 vec4), 6+6 loads per (cc,i)
            float4 h0 = *(const float4*)(cbh + coff[0]);
            uint4  q0 = *(const uint4*) (cbi + coff[0]);
            float4 h1 = *(const float4*)(cbh + coff[1]);
            uint4  q1 = *(const uint4*) (cbi + coff[1]);
            float4 h2 = *(const float4*)(cbh + coff[2]);
            uint4  q2 = *(const uint4*) (cbi + coff[2]);
            float4 h3 = *(const float4*)(cbh + coff[3]);
            uint4  q3 = *(const uint4*) (cbi + coff[3]);
            float4 wvh; uint4 wvi;
            // j = 0
            wvh = *(const float4*)(wrowb + (i * 3 + 0) * 64 + ch * 16);
            wvi = *(const uint4*) (wrowb + (i * 3 + 0) * 64 + ci * 16);
            ACC_MIX(0, h0, q0);
            ACC_MIX(1, h1, q1);
            ACC_MIX(2, h2, q2);
            ACC_MIX(3, h3, q3);
            h0 = *(const float4*)(cbh + coff[4]);
            q0 = *(const uint4*) (cbi + coff[4]);
            // j = 1
            wvh = *(const float4*)(wrowb + (i * 3 + 1) * 64 + ch * 16);
            wvi = *(const uint4*) (wrowb + (i * 3 + 1) * 64 + ci * 16);
            ACC_MIX(0, h1, q1);
            ACC_MIX(1, h2, q2);
            ACC_MIX(2, h3, q3);
            ACC_MIX(3, h0, q0);
            h1 = *(const float4*)(cbh + coff[5]);
            q1 = *(const uint4*) (cbi + coff[5]);
            // j = 2
            wvh = *(const float4*)(wrowb + (i * 3 + 2) * 64 + ch * 16);
            wvi = *(const uint4*) (wrowb + (i * 3 + 2) * 64 + ci * 16);
            ACC_MIX(0, h2, q2);
            ACC_MIX(1, h3, q3);
            ACC_MIX(2, h0, q0);
            ACC_MIX(3, h1, q1);
        }
    }

    // ---- merge domains in fp32, add bias, store ----
    const float bv = __ldg(bias + fq * FQ_ + fl);
    #pragma unroll
    for (int t = 0; t < 4; ++t) {
        int wo = wo_base + t;
        if (wo < WO_) {
            float hx = fmaxf(__low2float(mx2[t]), __high2float(mx2[t]));
            float hn = fminf(__low2float(mn2[t]), __high2float(mn2[t]));
            int mx = (int)mxi[t], mn = (int)mni[t];
            int ix = max((mx << 16) >> 16, mx >> 16);
            int in_ = min((mn << 16) >> 16, mn >> 16);
            float fx = fmaxf(hx, (float)ix * INVSC);
            float fn = fminf(hn, (float)in_ * INVSC);
            out[(row * WO_ + wo) * F_ + fq * FQ_ + fl] = fx - fn + bv;
        }
    }
}

extern "C" void kernel_launch(void* const* d_in, const int* in_sizes, int n_in,
                              void* d_out, int out_size)
{
    const float* x    = (const float*)d_in[0];
    const float* w    = (const float*)d_in[1];
    const float* bias = (const float*)d_in[2];
    float* out        = (float*)d_out;

    tropconv_hyb<<<B_ * HO_ * 4, 128>>>(x, w, bias, out);
}